// round 17
// baseline (speedup 1.0000x reference)
#include <cuda_runtime.h>

#define NB    4
#define NP    4096
#define TR    128                   // rows per block
#define CB    1024                  // cols per block
#define CTILE 128                   // cols per inner tile
#define NTC   (CB / CTILE)          // 8 inner tiles
#define RT    8                     // rows per thread
#define CT    8                     // cols per thread per tile
#define CCH   4                     // col chunk (register-liveness cap)
#define NMIN  (2 * NB * NP)         // 32768 mins: [gt rows | coord cols]
#define NBLK  (NB * (NP / TR) * (NP / CB))   // 512 blocks

// Keys are ~float_bits(d): atomicMax identity is 0 == the zero-initialized
// state. The last block resets everything to 0 (graph-replay clean).
__device__ unsigned g_key[NMIN];
__device__ unsigned g_count = 0;

__global__ __launch_bounds__(256) void chamfer_tile_kernel(
    const float* __restrict__ coord, const float* __restrict__ gt,
    float* __restrict__ out)
{
    __shared__ float sgx[TR], sgy[TR], sgz[TR], sgn[TR];
    __shared__ float scx2[CB], scy2[CB], scz2[CB], scn[CB];
    __shared__ unsigned srk[TR];
    __shared__ float red[8];
    __shared__ int is_last;

    const int b    = blockIdx.z;
    const int row0 = blockIdx.y * TR;   // gt rows
    const int col0 = blockIdx.x * CB;   // coord cols
    const int t    = threadIdx.x;

    // ---- stage once: 128 gt rows + 1024 coord cols (pre-transformed) ----
    if (t < TR) {
        const float* p = gt + (size_t)(b * NP + row0 + t) * 3;
        const float x = p[0], y = p[1], z = p[2];
        sgx[t] = x; sgy[t] = y; sgz[t] = z;
        sgn[t] = fmaf(x, x, fmaf(y, y, z * z));
        srk[t] = 0u;
    }
    for (int c = t; c < CB; c += 256) {
        const float* p = coord + (size_t)(b * NP + col0 + c) * 3;
        const float x = p[0], y = p[1], z = p[2];
        scx2[c] = -2.0f * x; scy2[c] = -2.0f * y; scz2[c] = -2.0f * z;
        scn[c]  = fmaf(x, x, fmaf(y, y, z * z));
    }
    __syncthreads();

    // txr indexes rows (persistent mins, folded once at block end);
    // tyc indexes cols (folded per tile via shfl across txr lanes).
    const int tyc = t >> 4;             // 0..15
    const int txr = t & 15;             // 0..15 (lane bits 0-3)

    float rx[RT], ry[RT], rz[RT], rn[RT];
#pragma unroll
    for (int i = 0; i < RT; i++) {
        const int r = txr + 16 * i;     // strided: conflict-free LDS
        rx[i] = sgx[r]; ry[i] = sgy[r]; rz[i] = sgz[r]; rn[i] = sgn[r];
    }

    const float INF = __int_as_float(0x7F800000);
    float rmin[RT];
#pragma unroll
    for (int i = 0; i < RT; i++) rmin[i] = INF;

    // ---- 8 col tiles, no syncs: d = (rn+cn) -2(rx cx + ry cy + rz cz) ----
#pragma unroll
    for (int kt = 0; kt < NTC; kt++) {
        const int base = kt * CTILE;
        float cm[CT];
#pragma unroll
        for (int q = 0; q < CT; q++) cm[q] = INF;

#pragma unroll
        for (int q0 = 0; q0 < CT; q0 += CCH) {
            float cx[CCH], cy[CCH], cz[CCH], cn[CCH];
#pragma unroll
            for (int qq = 0; qq < CCH; qq++) {
                const int c = base + tyc + 16 * (q0 + qq);  // strided: no conflicts
                cx[qq] = scx2[c]; cy[qq] = scy2[c]; cz[qq] = scz2[c]; cn[qq] = scn[c];
            }
#pragma unroll
            for (int i = 0; i < RT; i++) {
#pragma unroll
                for (int qq = 0; qq < CCH; qq++) {
                    float d = rn[i] + cn[qq];
                    d = fmaf(rx[i], cx[qq], d);
                    d = fmaf(ry[i], cy[qq], d);
                    d = fmaf(rz[i], cz[qq], d);
                    rmin[i] = fminf(rmin[i], d);
                    cm[q0 + qq] = fminf(cm[q0 + qq], d);
                }
            }
        }

        // Fold col mins across txr (lane bits 0-3), publish one REDG per col.
#pragma unroll
        for (int q = 0; q < CT; q++) {
            float v = cm[q];
            v = fminf(v, __shfl_xor_sync(0xFFFFFFFFu, v, 1));
            v = fminf(v, __shfl_xor_sync(0xFFFFFFFFu, v, 2));
            v = fminf(v, __shfl_xor_sync(0xFFFFFFFFu, v, 4));
            v = fminf(v, __shfl_xor_sync(0xFFFFFFFFu, v, 8));
            cm[q] = v;
        }
        if (txr == 0) {
#pragma unroll
            for (int q = 0; q < CT; q++) {
                const int c = base + tyc + 16 * q;
                atomicMax(&g_key[NB * NP + b * NP + col0 + c],
                          ~__float_as_uint(fmaxf(cm[q], 0.0f)));
            }
        }
    }

    // ---- row mins: smem fold across tyc groups, publish once per row ----
#pragma unroll
    for (int i = 0; i < RT; i++)
        atomicMax(&srk[txr + 16 * i], ~__float_as_uint(fmaxf(rmin[i], 0.0f)));
    __syncthreads();
    if (t < TR)
        atomicMax(&g_key[b * NP + row0 + t], srk[t]);

    // ---- fused last-block reduction (512 blocks -> cheap fence) ----
    __threadfence();
    __syncthreads();
    if (t == 0) {
        unsigned ticket = atomicAdd(&g_count, 1u);
        is_last = (ticket == (unsigned)(NBLK - 1));
    }
    __syncthreads();
    if (!is_last) return;

    // All prior blocks' atomics visible (fence + ticket). Sum and reset.
    float s = 0.0f;
    const uint4* pk = (const uint4*)g_key;
    uint4* pw = (uint4*)g_key;
    const uint4 zero4 = make_uint4(0u, 0u, 0u, 0u);
#pragma unroll
    for (int it = 0; it < NMIN / 4 / 256; it++) {     // 32 independent loads/thread
        const int i = it * 256 + t;
        uint4 v = __ldcg(&pk[i]);
        s += __uint_as_float(~v.x) + __uint_as_float(~v.y)
           + __uint_as_float(~v.z) + __uint_as_float(~v.w);
        pw[i] = zero4;                                 // reset for next replay
    }
#pragma unroll
    for (int m = 16; m; m >>= 1)
        s += __shfl_xor_sync(0xFFFFFFFFu, s, m);
    if ((t & 31) == 0) red[t >> 5] = s;
    __syncthreads();
    if (t == 0) {
        float tot = 0.0f;
#pragma unroll
        for (int w = 0; w < 8; w++) tot += red[w];
        // mean(match_coord) + mean(match_gt); B*M == B*N == 16384
        out[0] = tot * (1.0f / (float)(NB * NP));
        g_count = 0u;                                  // reset for next replay
    }
}

extern "C" void kernel_launch(void* const* d_in, const int* in_sizes, int n_in,
                              void* d_out, int out_size) {
    (void)in_sizes; (void)n_in; (void)out_size;
    const float* coord = (const float*)d_in[0];  // [B, N, 3]
    const float* gt    = (const float*)d_in[1];  // [B, M, 3]
    dim3 grid(NP / CB, NP / TR, NB);             // (4, 32, 4) = 512 blocks
    chamfer_tile_kernel<<<grid, 256>>>(coord, gt, (float*)d_out);
}